// round 3
// baseline (speedup 1.0000x reference)
#include <cuda_runtime.h>
#include <math.h>

// ChamferLoss: B=8, N=M=4096, D=3
// d_in[0] = predicted [8,4096,3] f32, d_in[1] = target [8,4096,3] f32, out = scalar f32

#define BATCH    8
#define NPTS     4096
#define THREADS  64
#define PPT      4                    // source points per thread
#define NGROUPS  (NPTS / 2)           // 2048 packed 2-target groups
#define NBLOCKS  256                  // 16 combos (b,dir) x 16 slices of 256 points
#define SMEM_BYTES (NGROUPS * 2 * (int)sizeof(ulonglong2))   // 64 KB

__device__ double       g_sum  = 0.0;
__device__ unsigned int g_tick = 0;

static __device__ __forceinline__ unsigned long long pk2(float lo, float hi) {
    unsigned long long r;
    asm("mov.b64 %0, {%1, %2};" : "=l"(r) : "f"(lo), "f"(hi));
    return r;
}
static __device__ __forceinline__ unsigned long long fma2(unsigned long long a,
                                                          unsigned long long b,
                                                          unsigned long long c) {
    unsigned long long d;
    asm("fma.rn.f32x2 %0, %1, %2, %3;" : "=l"(d) : "l"(a), "l"(b), "l"(c));
    return d;
}
static __device__ __forceinline__ void unpk2(unsigned long long v, float& lo, float& hi) {
    asm("mov.b64 {%0, %1}, %2;" : "=f"(lo), "=f"(hi) : "l"(v));
}

__global__ __launch_bounds__(THREADS) void chamfer_kernel(
    const float* __restrict__ pred,
    const float* __restrict__ targ,
    float* __restrict__ out)
{
    extern __shared__ ulonglong2 sm[];     // [2*NGROUPS]: {x0x1,y0y1},{z0z1,w0w1}
    __shared__ float warpsums[THREADS / 32];

    const int combo = blockIdx.x >> 4;     // 0..15 = (batch, dir)
    const int slice = blockIdx.x & 15;     // 0..15
    const int dir   = combo & 1;
    const int b     = combo >> 1;
    const float* __restrict__ sp = (dir == 0 ? pred : targ) + (size_t)b * NPTS * 3;
    const float* __restrict__ tp = (dir == 0 ? targ : pred) + (size_t)b * NPTS * 3;

    // Stage the full 4096-point target cloud as packed pair-groups (x,y,z,|t|^2)
    for (int g = threadIdx.x; g < NGROUPS; g += THREADS) {
        const float* t = tp + 6 * g;
        float x0 = t[0], y0 = t[1], z0 = t[2];
        float x1 = t[3], y1 = t[4], z1 = t[5];
        float w0 = fmaf(x0, x0, fmaf(y0, y0, z0 * z0));
        float w1 = fmaf(x1, x1, fmaf(y1, y1, z1 * z1));
        sm[2 * g]     = make_ulonglong2(pk2(x0, x1), pk2(y0, y1));
        sm[2 * g + 1] = make_ulonglong2(pk2(z0, z1), pk2(w0, w1));
    }

    // This thread's PPT source points (stride THREADS within the 256-point slice)
    unsigned long long mx[PPT], my[PPT], mz[PPT];
    float p2[PPT];
    #pragma unroll
    for (int p = 0; p < PPT; p++) {
        const int i = slice * (THREADS * PPT) + p * THREADS + threadIdx.x;
        float px = sp[3 * i + 0];
        float py = sp[3 * i + 1];
        float pz = sp[3 * i + 2];
        mx[p] = pk2(-2.0f * px, -2.0f * px);
        my[p] = pk2(-2.0f * py, -2.0f * py);
        mz[p] = pk2(-2.0f * pz, -2.0f * pz);
        p2[p] = fmaf(px, px, fmaf(py, py, pz * pz));
    }

    __syncthreads();

    float best0[PPT], best1[PPT];
    #pragma unroll
    for (int p = 0; p < PPT; p++) { best0[p] = INFINITY; best1[p] = INFINITY; }

    #pragma unroll 4
    for (int g = 0; g < NGROUPS; g++) {
        const ulonglong2 A = sm[2 * g];        // {x0x1, y0y1}
        const ulonglong2 C = sm[2 * g + 1];    // {z0z1, w0w1}
        #pragma unroll
        for (int p = 0; p < PPT; p++) {
            unsigned long long v = fma2(mz[p], C.x, C.y);
            v = fma2(my[p], A.y, v);
            v = fma2(mx[p], A.x, v);
            float vlo, vhi;
            unpk2(v, vlo, vhi);
            best0[p] = fminf(best0[p], vlo);
            best1[p] = fminf(best1[p], vhi);
        }
    }

    // Per-thread sum of min distances
    float s = 0.0f;
    #pragma unroll
    for (int p = 0; p < PPT; p++) {
        float d2 = fminf(best0[p], best1[p]) + p2[p];
        s += sqrtf(fmaxf(d2, 0.0f));
    }

    // Block reduction (2 warps)
    #pragma unroll
    for (int o = 16; o > 0; o >>= 1)
        s += __shfl_xor_sync(0xFFFFFFFFu, s, o);
    const int lane = threadIdx.x & 31;
    const int wid  = threadIdx.x >> 5;
    if (lane == 0) warpsums[wid] = s;
    __syncthreads();
    if (threadIdx.x == 0) {
        float v = warpsums[0] + warpsums[1];
        const double scale = 1.0 / ((double)BATCH * (double)NPTS);
        atomicAdd(&g_sum, (double)v * scale);
        __threadfence();
        unsigned int done = atomicAdd(&g_tick, 1u);
        if (done == NBLOCKS - 1) {
            double total = atomicAdd(&g_sum, 0.0);   // atomic read
            out[0] = (float)total;
            g_sum  = 0.0;                            // reset for next graph replay
            g_tick = 0;
        }
    }
}

extern "C" void kernel_launch(void* const* d_in, const int* in_sizes, int n_in,
                              void* d_out, int out_size) {
    const float* pred = (const float*)d_in[0];
    const float* targ = (const float*)d_in[1];
    float* out = (float*)d_out;

    static bool attr_set = false;
    if (!attr_set) {
        cudaFuncSetAttribute(chamfer_kernel,
                             cudaFuncAttributeMaxDynamicSharedMemorySize, SMEM_BYTES);
        attr_set = true;
    }

    chamfer_kernel<<<NBLOCKS, THREADS, SMEM_BYTES>>>(pred, targ, out);
}

// round 4
// speedup vs baseline: 1.7580x; 1.7580x over previous
#include <cuda_runtime.h>
#include <math.h>

// ChamferLoss: B=8, N=M=4096, D=3
// d_in[0] = predicted [8,4096,3] f32, d_in[1] = target [8,4096,3] f32, out = scalar f32

#define BATCH    8
#define NPTS     4096
#define THREADS  128
#define PPT      4                    // source points per thread
#define TCHUNK   512                  // targets per block (8 KB smem)
#define TGROUPS  (TCHUNK / 2)         // 256 packed 2-target groups
#define NCOMBO   16                   // 8 batches x 2 directions
#define SRCSLICES 8                   // 8 x 512 source points
#define TCHUNKS  (NPTS / TCHUNK)      // 8
#define NBLOCKS  (NCOMBO * SRCSLICES * TCHUNKS)   // 1024
#define NMIN     (NCOMBO * NPTS)      // 65536 min slots

__device__ unsigned int g_minbuf[NMIN];   // squared-dist bits (nonneg -> uint-ordered)

static __device__ __forceinline__ unsigned long long pk2(float lo, float hi) {
    unsigned long long r;
    asm("mov.b64 %0, {%1, %2};" : "=l"(r) : "f"(lo), "f"(hi));
    return r;
}
static __device__ __forceinline__ unsigned long long fma2(unsigned long long a,
                                                          unsigned long long b,
                                                          unsigned long long c) {
    unsigned long long d;
    asm("fma.rn.f32x2 %0, %1, %2, %3;" : "=l"(d) : "l"(a), "l"(b), "l"(c));
    return d;
}
static __device__ __forceinline__ void unpk2(unsigned long long v, float& lo, float& hi) {
    asm("mov.b64 {%0, %1}, %2;" : "=f"(lo), "=f"(hi) : "l"(v));
}

__global__ void init_kernel() {
    int i = blockIdx.x * blockDim.x + threadIdx.x;
    g_minbuf[i] = 0x7F800000u;   // +inf
}

__global__ __launch_bounds__(THREADS) void chamfer_kernel(
    const float* __restrict__ pred,
    const float* __restrict__ targ)
{
    __shared__ ulonglong2 sm[2 * TGROUPS];   // {x0x1,y0y1},{z0z1,w0w1} per group

    const int bx     = blockIdx.x;
    const int combo  = bx >> 6;          // 0..15
    const int sslice = (bx >> 3) & 7;    // 0..7
    const int tchunk = bx & 7;           // 0..7
    const int dir    = combo & 1;
    const int b      = combo >> 1;
    const float* __restrict__ sp = (dir == 0 ? pred : targ) + (size_t)b * NPTS * 3;
    const float* __restrict__ tp = (dir == 0 ? targ : pred) + (size_t)b * NPTS * 3;

    // Stage this block's 512-target chunk as packed pair-groups (x,y,z,|t|^2)
    const float* tc = tp + (size_t)tchunk * TCHUNK * 3;
    #pragma unroll
    for (int g = threadIdx.x; g < TGROUPS; g += THREADS) {
        const float* t = tc + 6 * g;
        float x0 = t[0], y0 = t[1], z0 = t[2];
        float x1 = t[3], y1 = t[4], z1 = t[5];
        float w0 = fmaf(x0, x0, fmaf(y0, y0, z0 * z0));
        float w1 = fmaf(x1, x1, fmaf(y1, y1, z1 * z1));
        sm[2 * g]     = make_ulonglong2(pk2(x0, x1), pk2(y0, y1));
        sm[2 * g + 1] = make_ulonglong2(pk2(z0, z1), pk2(w0, w1));
    }

    // This thread's PPT source points
    unsigned long long mx[PPT], my[PPT], mz[PPT];
    float p2[PPT];
    int   sidx[PPT];
    #pragma unroll
    for (int p = 0; p < PPT; p++) {
        const int i = sslice * (THREADS * PPT) + p * THREADS + threadIdx.x;
        sidx[p] = combo * NPTS + i;
        float px = sp[3 * i + 0];
        float py = sp[3 * i + 1];
        float pz = sp[3 * i + 2];
        mx[p] = pk2(-2.0f * px, -2.0f * px);
        my[p] = pk2(-2.0f * py, -2.0f * py);
        mz[p] = pk2(-2.0f * pz, -2.0f * pz);
        p2[p] = fmaf(px, px, fmaf(py, py, pz * pz));
    }

    __syncthreads();

    float best0[PPT], best1[PPT];
    #pragma unroll
    for (int p = 0; p < PPT; p++) { best0[p] = INFINITY; best1[p] = INFINITY; }

    #pragma unroll 4
    for (int g = 0; g < TGROUPS; g++) {
        const ulonglong2 A = sm[2 * g];        // {x0x1, y0y1}
        const ulonglong2 C = sm[2 * g + 1];    // {z0z1, w0w1}
        #pragma unroll
        for (int p = 0; p < PPT; p++) {
            unsigned long long v = fma2(mz[p], C.x, C.y);
            v = fma2(my[p], A.y, v);
            v = fma2(mx[p], A.x, v);
            float vlo, vhi;
            unpk2(v, vlo, vhi);
            best0[p] = fminf(best0[p], vlo);
            best1[p] = fminf(best1[p], vhi);
        }
    }

    // Publish partial min squared distance (nonneg -> uint order == float order)
    #pragma unroll
    for (int p = 0; p < PPT; p++) {
        float d2 = fmaxf(fminf(best0[p], best1[p]) + p2[p], 0.0f);
        atomicMin(&g_minbuf[sidx[p]], __float_as_uint(d2));
    }
}

__global__ __launch_bounds__(1024) void reduce_kernel(float* __restrict__ out) {
    __shared__ float warpsums[32];
    const int tid = threadIdx.x;

    float s = 0.0f;
    const uint4* buf = (const uint4*)g_minbuf;
    #pragma unroll
    for (int k = 0; k < NMIN / 4 / 1024; k++) {     // 16 iterations
        uint4 v = buf[k * 1024 + tid];
        s += sqrtf(__uint_as_float(v.x)) + sqrtf(__uint_as_float(v.y))
           + sqrtf(__uint_as_float(v.z)) + sqrtf(__uint_as_float(v.w));
    }
    #pragma unroll
    for (int o = 16; o > 0; o >>= 1)
        s += __shfl_xor_sync(0xFFFFFFFFu, s, o);
    const int lane = tid & 31, wid = tid >> 5;
    if (lane == 0) warpsums[wid] = s;
    __syncthreads();
    if (wid == 0) {
        float v = warpsums[lane];
        #pragma unroll
        for (int o = 16; o > 0; o >>= 1)
            v += __shfl_xor_sync(0xFFFFFFFFu, v, o);
        if (lane == 0)
            out[0] = (float)((double)v / ((double)BATCH * (double)NPTS));
    }
}

extern "C" void kernel_launch(void* const* d_in, const int* in_sizes, int n_in,
                              void* d_out, int out_size) {
    const float* pred = (const float*)d_in[0];
    const float* targ = (const float*)d_in[1];
    float* out = (float*)d_out;

    init_kernel<<<NMIN / 256, 256>>>();
    chamfer_kernel<<<NBLOCKS, THREADS>>>(pred, targ);
    reduce_kernel<<<1, 1024>>>(out);
}